// round 5
// baseline (speedup 1.0000x reference)
#include <cuda_runtime.h>

#define BATCH 1024
#define RC 64
#define NL 24
#define QL 128
#define TB 4                     // batch rows per compute block
#define NCOMP (BATCH / TB)       // 256 compute blocks
#define NTHREADS 256
#define NQ ((size_t)NL * BATCH * RC * QL)   // 201326592 queue elements
#define NROWS (NQ / 128)                    // 1572864 rows of 128 floats
#define RPW 64                              // rows per copy warp
#define WARPS_PER_BLK 8
#define NCOPY ((int)(NROWS / (RPW * WARPS_PER_BLK)))   // 3072 copy blocks
#define LSTR ((size_t)BATCH * RC)           // row index stride per layer

__device__ __forceinline__ float sigf(float x) { return 1.0f / (1.0f + __expf(-x)); }

// Store one 128-float row (held as float4 v per lane) to dstq + R*129,
// realigned so the bulk goes out as one aligned STG.128 per lane.
__device__ __forceinline__ void store_row(float* __restrict__ dstq, size_t R,
                                          int lane, float4 v)
{
    float* base = dstq + R * 129;
    unsigned m = (unsigned)(R & 3);          // base misalignment in floats
    if (m == 0) {
        *(float4*)(base + 4 * lane) = v;
        return;
    }
    unsigned s = 4 - m;                      // shift: first aligned float index
    float nx = __shfl_down_sync(0xffffffffu, v.x, 1);
    float ny = __shfl_down_sync(0xffffffffu, v.y, 1);
    float nz = __shfl_down_sync(0xffffffffu, v.z, 1);
    float4 w;
    if (s == 1)      w = make_float4(v.y, v.z, v.w, nx);
    else if (s == 2) w = make_float4(v.z, v.w, nx, ny);
    else             w = make_float4(v.w, nx, ny, nz);
    if (lane < 31)
        *(float4*)(base + s + 4 * lane) = w; // 16B-aligned bulk
    if (lane == 0) {                         // head floats j = 0..s-1
        base[0] = v.x;
        if (s >= 2) base[1] = v.y;
        if (s >= 3) base[2] = v.z;
    }
    if (lane == 31) {                        // tail floats j = s+124..127
        base[127] = v.w;
        if (s <= 2) base[126] = v.z;
        if (s <= 1) base[125] = v.y;
    }
}

// ---------------------------------------------------------------------------
// COPY KERNEL: queues (.., 128) -> out queue region (.., 129), t < 128.
// Each warp owns RPW contiguous rows; 4-row unroll -> 2KB contiguous reads.
// (Proven: 313us standalone, 5.1 TB/s, occ 88%.)
// ---------------------------------------------------------------------------
__global__ void __launch_bounds__(NTHREADS)
queue_copy_kernel(const float* __restrict__ queues, float* __restrict__ out)
{
    const float4* __restrict__ src = (const float4*)queues;
    float* __restrict__ dstq = out + BATCH;
    const int lane = threadIdx.x & 31;
    size_t R = ((size_t)blockIdx.x * WARPS_PER_BLK + (threadIdx.x >> 5)) * RPW;

    #pragma unroll 1
    for (int it = 0; it < RPW / 4; it++, R += 4) {
        float4 v0 = __ldcs(&src[(R)     * 32 + lane]);
        float4 v1 = __ldcs(&src[(R + 1) * 32 + lane]);
        float4 v2 = __ldcs(&src[(R + 2) * 32 + lane]);
        float4 v3 = __ldcs(&src[(R + 3) * 32 + lane]);
        store_row(dstq, R,     lane, v0);
        store_row(dstq, R + 1, lane, v1);
        store_row(dstq, R + 2, lane, v2);
        store_row(dstq, R + 3, lane, v3);
    }
}

// ---------------------------------------------------------------------------
// COMPUTE KERNEL: recurrent WaveNet cell, TB=4 batch rows per block.
// All 24 dilated queue-slice loads are prefetched into registers up front
// (they depend only on the input), so the serial layer loop has no exposed
// DRAM latency even while the copy kernel saturates HBM.
// ---------------------------------------------------------------------------
__global__ void __launch_bounds__(NTHREADS)
wave_compute_kernel(const float* __restrict__ x,
                    const float* __restrict__ features,
                    const float* __restrict__ queues,
                    const float* __restrict__ fc_h_w,
                    const float* __restrict__ fc_h_b,
                    const float* __restrict__ fc_c_w,
                    const float* __restrict__ fc_c_b,
                    const float* __restrict__ conv_w,
                    const float* __restrict__ conv_b,
                    const float* __restrict__ fc1_w,
                    const float* __restrict__ fc1_b,
                    const float* __restrict__ fc2_w,
                    const float* __restrict__ fc2_b,
                    float* __restrict__ out)
{
    __shared__ __align__(16) float s_h[TB][RC];
    __shared__ __align__(16) float s_c[TB][RC];
    __shared__ __align__(16) float s_prev[TB][RC];
    __shared__ float s_co[TB][4 * RC];

    const int tid = threadIdx.x;
    const int b0  = blockIdx.x * TB;
    const int j   = tid;
    const int t   = tid >> 6;          // this thread's (t, r) slice element
    const int r   = tid & 63;
    const int b   = b0 + t;

    // ---- prefetch ALL 24 layers' dilated queue values (input-only) ----
    float pv[NL];
    {
        const size_t base = ((size_t)b * RC + r) * QL + QL; // + QL, minus d below
        #pragma unroll
        for (int i = 0; i < NL; i++)
            pv[i] = __ldg(queues + base + (size_t)i * (LSTR * QL) - (1 << (i & 7)));
    }

    // ---- initial h, c = tanh(inp @ W^T + b), inp = [x, features] (33) ----
    float* __restrict__ outq = out + BATCH;
    const size_t ebase = (size_t)b * RC + r;   // entry-store row index base
    {
        const float* wh = fc_h_w + r * 33;
        const float* wc = fc_c_w + r * 33;
        float ah = fc_h_b[r], ac = fc_c_b[r];
        float xv = x[b];
        ah += xv * wh[0];
        ac += xv * wc[0];
        const float* fb = features + b * 32;
        #pragma unroll
        for (int k = 0; k < 32; k++) {
            float f = fb[k];
            ah += f * wh[1 + k];
            ac += f * wc[1 + k];
        }
        float h0 = tanhf(ah);
        s_h[t][r] = h0;
        s_c[t][r] = tanhf(ac);
        outq[ebase * 129 + QL] = h0;           // entry for layer 0
    }

    float yacc[TB];
    #pragma unroll
    for (int tt = 0; tt < TB; tt++) yacc[tt] = fc1_b[j];
    __syncthreads();

    for (int i = 0; i < NL; i++) {
        // ---- publish this layer's prev slice (already in registers) ----
        s_prev[t][r] = pv[i];
        __syncthreads();

        // ---- co[tt][j] = prev @ W0^T + h @ W1^T + b  (weights via L2) ----
        float acc[TB];
        {
            float bias = conv_b[i * 256 + j];
            #pragma unroll
            for (int tt = 0; tt < TB; tt++) acc[tt] = bias;
        }
        const float4* __restrict__ wrow =
            (const float4*)(conv_w + (size_t)(i * 256 + j) * 128); // [r][2] interleaved
        #pragma unroll 4
        for (int rc = 0; rc < RC; rc += 4) {
            float4 wa = wrow[rc >> 1];       // w0[rc], w1[rc], w0[rc+1], w1[rc+1]
            float4 wb = wrow[(rc >> 1) + 1];
            #pragma unroll
            for (int tt = 0; tt < TB; tt++) {
                float4 p  = *(const float4*)&s_prev[tt][rc];
                float4 hh = *(const float4*)&s_h[tt][rc];
                float a = acc[tt];
                a += p.x * wa.x + hh.x * wa.y;
                a += p.y * wa.z + hh.y * wa.w;
                a += p.z * wb.x + hh.z * wb.y;
                a += p.w * wb.z + hh.w * wb.w;
                acc[tt] = a;
            }
        }
        #pragma unroll
        for (int tt = 0; tt < TB; tt++) s_co[tt][j] = acc[tt];
        __syncthreads();

        // ---- gate update (one element per thread); write next entry ----
        {
            float ig = s_co[t][r];
            float cf = s_co[t][RC + r];
            float cg = s_co[t][2 * RC + r];
            float eg = s_co[t][3 * RC + r];
            float c = sigf(ig) * s_c[t][r] + tanhf(cf) * sigf(cg);
            float h = sigf(eg) * tanhf(c);
            s_c[t][r] = c;
            s_h[t][r] = h;
            if (i + 1 < NL)                    // entry_h for layer i+1
                outq[(ebase + (size_t)(i + 1) * LSTR) * 129 + QL] = h;
        }
        __syncthreads();

        // ---- incremental fc1: yacc[tt] += h[tt] @ fc1_w[j, i*64 : +64] ----
        const float4* __restrict__ f1 =
            (const float4*)(fc1_w + (size_t)j * (NL * RC) + i * RC);
        #pragma unroll 4
        for (int rc = 0; rc < RC; rc += 4) {
            float4 w = f1[rc >> 2];
            #pragma unroll
            for (int tt = 0; tt < TB; tt++) {
                float4 hh = *(const float4*)&s_h[tt][rc];
                yacc[tt] += hh.x * w.x + hh.y * w.y + hh.z * w.z + hh.w * w.w;
            }
        }
        // no barrier: next iteration writes s_prev (not touched here) and the
        // following barrier protects s_h reuse
    }

    // ---- fc2: h_hat[b] = relu(y) @ fc2_w^T + fc2_b ----
    #pragma unroll
    for (int tt = 0; tt < TB; tt++)
        s_co[tt][j] = fmaxf(yacc[tt], 0.0f) * fc2_w[j];
    __syncthreads();

    int w = tid >> 5, lane = tid & 31;
    if (w < TB) {                        // warps 0..3 reduce the TB rows
        float s = 0.0f;
        #pragma unroll
        for (int k = 0; k < 8; k++) s += s_co[w][lane + k * 32];
        #pragma unroll
        for (int o = 16; o > 0; o >>= 1) s += __shfl_xor_sync(0xffffffffu, s, o);
        if (lane == 0) out[b0 + w] = s + fc2_b[0];
    }
}

extern "C" void kernel_launch(void* const* d_in, const int* in_sizes, int n_in,
                              void* d_out, int out_size)
{
    const float* x        = (const float*)d_in[0];
    const float* features = (const float*)d_in[1];
    const float* queues   = (const float*)d_in[2];
    const float* fc_h_w   = (const float*)d_in[3];
    const float* fc_h_b   = (const float*)d_in[4];
    const float* fc_c_w   = (const float*)d_in[5];
    const float* fc_c_b   = (const float*)d_in[6];
    const float* conv_w   = (const float*)d_in[7];
    const float* conv_b   = (const float*)d_in[8];
    const float* fc1_w    = (const float*)d_in[9];
    const float* fc1_b    = (const float*)d_in[10];
    const float* fc2_w    = (const float*)d_in[11];
    const float* fc2_b    = (const float*)d_in[12];
    float* out = (float*)d_out;

    // Fork a second stream so copy and compute run concurrently in the graph.
    cudaStream_t s1;
    cudaStreamCreateWithFlags(&s1, cudaStreamNonBlocking);
    cudaEvent_t evFork, evJoin;
    cudaEventCreateWithFlags(&evFork, cudaEventDisableTiming);
    cudaEventCreateWithFlags(&evJoin, cudaEventDisableTiming);

    cudaEventRecord(evFork, 0);          // fork point (before any kernel)
    cudaStreamWaitEvent(s1, evFork, 0);

    // Copy is the critical path: launch it first, on the main stream.
    queue_copy_kernel<<<NCOPY, NTHREADS>>>(queues, out);

    wave_compute_kernel<<<NCOMP, NTHREADS, 0, s1>>>(
        x, features, queues, fc_h_w, fc_h_b, fc_c_w, fc_c_b,
        conv_w, conv_b, fc1_w, fc1_b, fc2_w, fc2_b, out);

    cudaEventRecord(evJoin, s1);         // join compute stream back
    cudaStreamWaitEvent(0, evJoin, 0);

    cudaStreamDestroy(s1);
    cudaEventDestroy(evFork);
    cudaEventDestroy(evJoin);
}

// round 6
// speedup vs baseline: 1.0011x; 1.0011x over previous
#include <cuda_runtime.h>

#define BATCH 1024
#define RC 64
#define NL 24
#define QL 128
#define TB 4                     // batch rows per compute block
#define NCOMP (BATCH / TB)       // 256 compute blocks
#define NTHREADS 256
#define NQ ((size_t)NL * BATCH * RC * QL)   // 201326592 queue elements
#define NROWS (NQ / 128)                    // 1572864 rows of 128 floats
#define RPW 64                              // rows per copy warp
#define WARPS_PER_BLK 8
#define NCOPY ((int)(NROWS / (RPW * WARPS_PER_BLK)))   // 3072 copy blocks
#define LSTR ((size_t)BATCH * RC)           // row index stride per layer

__device__ __forceinline__ float sigf(float x) { return 1.0f / (1.0f + __expf(-x)); }

// Store one 128-float row (held as float4 v per lane) to dstq + R*129,
// realigned so the bulk goes out as one aligned STG.128 per lane.
__device__ __forceinline__ void store_row(float* __restrict__ dstq, size_t R,
                                          int lane, float4 v)
{
    float* base = dstq + R * 129;
    unsigned m = (unsigned)(R & 3);          // base misalignment in floats
    if (m == 0) {
        *(float4*)(base + 4 * lane) = v;
        return;
    }
    unsigned s = 4 - m;                      // shift: first aligned float index
    float nx = __shfl_down_sync(0xffffffffu, v.x, 1);
    float ny = __shfl_down_sync(0xffffffffu, v.y, 1);
    float nz = __shfl_down_sync(0xffffffffu, v.z, 1);
    float4 w;
    if (s == 1)      w = make_float4(v.y, v.z, v.w, nx);
    else if (s == 2) w = make_float4(v.z, v.w, nx, ny);
    else             w = make_float4(v.w, nx, ny, nz);
    if (lane < 31)
        *(float4*)(base + s + 4 * lane) = w; // 16B-aligned bulk
    if (lane == 0) {                         // head floats j = 0..s-1
        base[0] = v.x;
        if (s >= 2) base[1] = v.y;
        if (s >= 3) base[2] = v.z;
    }
    if (lane == 31) {                        // tail floats j = s+124..127
        base[127] = v.w;
        if (s <= 2) base[126] = v.z;
        if (s <= 1) base[125] = v.y;
    }
}

// ---------------------------------------------------------------------------
// COPY KERNEL: queues (.., 128) -> out queue region (.., 129), t < 128.
// Each warp owns RPW contiguous rows; 4-row unroll -> 2KB contiguous reads.
// (Proven: 313us standalone, 5.1 TB/s, occ 88%.)
// ---------------------------------------------------------------------------
__global__ void __launch_bounds__(NTHREADS)
queue_copy_kernel(const float* __restrict__ queues, float* __restrict__ out)
{
    const float4* __restrict__ src = (const float4*)queues;
    float* __restrict__ dstq = out + BATCH;
    const int lane = threadIdx.x & 31;
    size_t R = ((size_t)blockIdx.x * WARPS_PER_BLK + (threadIdx.x >> 5)) * RPW;

    #pragma unroll 1
    for (int it = 0; it < RPW / 4; it++, R += 4) {
        float4 v0 = __ldcs(&src[(R)     * 32 + lane]);
        float4 v1 = __ldcs(&src[(R + 1) * 32 + lane]);
        float4 v2 = __ldcs(&src[(R + 2) * 32 + lane]);
        float4 v3 = __ldcs(&src[(R + 3) * 32 + lane]);
        store_row(dstq, R,     lane, v0);
        store_row(dstq, R + 1, lane, v1);
        store_row(dstq, R + 2, lane, v2);
        store_row(dstq, R + 3, lane, v3);
    }
}

// ---------------------------------------------------------------------------
// COMPUTE KERNEL: recurrent WaveNet cell, TB=4 batch rows per block.
// All 24 dilated queue-slice loads are prefetched into registers up front
// (they depend only on the input), so the serial layer loop has no exposed
// DRAM latency even while the copy kernel saturates HBM.
// ---------------------------------------------------------------------------
__global__ void __launch_bounds__(NTHREADS)
wave_compute_kernel(const float* __restrict__ x,
                    const float* __restrict__ features,
                    const float* __restrict__ queues,
                    const float* __restrict__ fc_h_w,
                    const float* __restrict__ fc_h_b,
                    const float* __restrict__ fc_c_w,
                    const float* __restrict__ fc_c_b,
                    const float* __restrict__ conv_w,
                    const float* __restrict__ conv_b,
                    const float* __restrict__ fc1_w,
                    const float* __restrict__ fc1_b,
                    const float* __restrict__ fc2_w,
                    const float* __restrict__ fc2_b,
                    float* __restrict__ out)
{
    __shared__ __align__(16) float s_h[TB][RC];
    __shared__ __align__(16) float s_c[TB][RC];
    __shared__ __align__(16) float s_prev[TB][RC];
    __shared__ float s_co[TB][4 * RC];

    const int tid = threadIdx.x;
    const int b0  = blockIdx.x * TB;
    const int j   = tid;
    const int t   = tid >> 6;          // this thread's (t, r) slice element
    const int r   = tid & 63;
    const int b   = b0 + t;

    // ---- prefetch ALL 24 layers' dilated queue values (input-only) ----
    float pv[NL];
    {
        const size_t base = ((size_t)b * RC + r) * QL + QL; // + QL, minus d below
        #pragma unroll
        for (int i = 0; i < NL; i++)
            pv[i] = __ldg(queues + base + (size_t)i * (LSTR * QL) - (1 << (i & 7)));
    }

    // ---- initial h, c = tanh(inp @ W^T + b), inp = [x, features] (33) ----
    float* __restrict__ outq = out + BATCH;
    const size_t ebase = (size_t)b * RC + r;   // entry-store row index base
    {
        const float* wh = fc_h_w + r * 33;
        const float* wc = fc_c_w + r * 33;
        float ah = fc_h_b[r], ac = fc_c_b[r];
        float xv = x[b];
        ah += xv * wh[0];
        ac += xv * wc[0];
        const float* fb = features + b * 32;
        #pragma unroll
        for (int k = 0; k < 32; k++) {
            float f = fb[k];
            ah += f * wh[1 + k];
            ac += f * wc[1 + k];
        }
        float h0 = tanhf(ah);
        s_h[t][r] = h0;
        s_c[t][r] = tanhf(ac);
        outq[ebase * 129 + QL] = h0;           // entry for layer 0
    }

    float yacc[TB];
    #pragma unroll
    for (int tt = 0; tt < TB; tt++) yacc[tt] = fc1_b[j];
    __syncthreads();

    for (int i = 0; i < NL; i++) {
        // ---- publish this layer's prev slice (already in registers) ----
        s_prev[t][r] = pv[i];
        __syncthreads();

        // ---- co[tt][j] = prev @ W0^T + h @ W1^T + b  (weights via L2) ----
        float acc[TB];
        {
            float bias = conv_b[i * 256 + j];
            #pragma unroll
            for (int tt = 0; tt < TB; tt++) acc[tt] = bias;
        }
        const float4* __restrict__ wrow =
            (const float4*)(conv_w + (size_t)(i * 256 + j) * 128); // [r][2] interleaved
        #pragma unroll 4
        for (int rc = 0; rc < RC; rc += 4) {
            float4 wa = wrow[rc >> 1];       // w0[rc], w1[rc], w0[rc+1], w1[rc+1]
            float4 wb = wrow[(rc >> 1) + 1];
            #pragma unroll
            for (int tt = 0; tt < TB; tt++) {
                float4 p  = *(const float4*)&s_prev[tt][rc];
                float4 hh = *(const float4*)&s_h[tt][rc];
                float a = acc[tt];
                a += p.x * wa.x + hh.x * wa.y;
                a += p.y * wa.z + hh.y * wa.w;
                a += p.z * wb.x + hh.z * wb.y;
                a += p.w * wb.z + hh.w * wb.w;
                acc[tt] = a;
            }
        }
        #pragma unroll
        for (int tt = 0; tt < TB; tt++) s_co[tt][j] = acc[tt];
        __syncthreads();

        // ---- gate update (one element per thread); write next entry ----
        {
            float ig = s_co[t][r];
            float cf = s_co[t][RC + r];
            float cg = s_co[t][2 * RC + r];
            float eg = s_co[t][3 * RC + r];
            float c = sigf(ig) * s_c[t][r] + tanhf(cf) * sigf(cg);
            float h = sigf(eg) * tanhf(c);
            s_c[t][r] = c;
            s_h[t][r] = h;
            if (i + 1 < NL)                    // entry_h for layer i+1
                outq[(ebase + (size_t)(i + 1) * LSTR) * 129 + QL] = h;
        }
        __syncthreads();

        // ---- incremental fc1: yacc[tt] += h[tt] @ fc1_w[j, i*64 : +64] ----
        const float4* __restrict__ f1 =
            (const float4*)(fc1_w + (size_t)j * (NL * RC) + i * RC);
        #pragma unroll 4
        for (int rc = 0; rc < RC; rc += 4) {
            float4 w = f1[rc >> 2];
            #pragma unroll
            for (int tt = 0; tt < TB; tt++) {
                float4 hh = *(const float4*)&s_h[tt][rc];
                yacc[tt] += hh.x * w.x + hh.y * w.y + hh.z * w.z + hh.w * w.w;
            }
        }
        // no barrier: next iteration writes s_prev (not touched here) and the
        // following barrier protects s_h reuse
    }

    // ---- fc2: h_hat[b] = relu(y) @ fc2_w^T + fc2_b ----
    #pragma unroll
    for (int tt = 0; tt < TB; tt++)
        s_co[tt][j] = fmaxf(yacc[tt], 0.0f) * fc2_w[j];
    __syncthreads();

    int w = tid >> 5, lane = tid & 31;
    if (w < TB) {                        // warps 0..3 reduce the TB rows
        float s = 0.0f;
        #pragma unroll
        for (int k = 0; k < 8; k++) s += s_co[w][lane + k * 32];
        #pragma unroll
        for (int o = 16; o > 0; o >>= 1) s += __shfl_xor_sync(0xffffffffu, s, o);
        if (lane == 0) out[b0 + w] = s + fc2_b[0];
    }
}

extern "C" void kernel_launch(void* const* d_in, const int* in_sizes, int n_in,
                              void* d_out, int out_size)
{
    const float* x        = (const float*)d_in[0];
    const float* features = (const float*)d_in[1];
    const float* queues   = (const float*)d_in[2];
    const float* fc_h_w   = (const float*)d_in[3];
    const float* fc_h_b   = (const float*)d_in[4];
    const float* fc_c_w   = (const float*)d_in[5];
    const float* fc_c_b   = (const float*)d_in[6];
    const float* conv_w   = (const float*)d_in[7];
    const float* conv_b   = (const float*)d_in[8];
    const float* fc1_w    = (const float*)d_in[9];
    const float* fc1_b    = (const float*)d_in[10];
    const float* fc2_w    = (const float*)d_in[11];
    const float* fc2_b    = (const float*)d_in[12];
    float* out = (float*)d_out;

    // Fork a second stream so copy and compute run concurrently in the graph.
    cudaStream_t s1;
    cudaStreamCreateWithFlags(&s1, cudaStreamNonBlocking);
    cudaEvent_t evFork, evJoin;
    cudaEventCreateWithFlags(&evFork, cudaEventDisableTiming);
    cudaEventCreateWithFlags(&evJoin, cudaEventDisableTiming);

    cudaEventRecord(evFork, 0);          // fork point (before any kernel)
    cudaStreamWaitEvent(s1, evFork, 0);

    // Copy is the critical path: launch it first, on the main stream.
    queue_copy_kernel<<<NCOPY, NTHREADS>>>(queues, out);

    wave_compute_kernel<<<NCOMP, NTHREADS, 0, s1>>>(
        x, features, queues, fc_h_w, fc_h_b, fc_c_w, fc_c_b,
        conv_w, conv_b, fc1_w, fc1_b, fc2_w, fc2_b, out);

    cudaEventRecord(evJoin, s1);         // join compute stream back
    cudaStreamWaitEvent(0, evJoin, 0);

    cudaStreamDestroy(s1);
    cudaEventDestroy(evFork);
    cudaEventDestroy(evJoin);
}

// round 7
// speedup vs baseline: 1.7783x; 1.7762x over previous
#include <cuda_runtime.h>

#define BATCH 1024
#define RC 64
#define NL 24
#define QL 128
#define TB 4                     // batch rows per compute block
#define NCOMP (BATCH / TB)       // 256 compute blocks
#define NTHREADS 256
#define NQ ((size_t)NL * BATCH * RC * QL)   // 201326592 queue elements
#define NROWS (NQ / 128)                    // 1572864 rows of 128 floats
#define RPW 64                              // rows per copy warp
#define WARPS_PER_BLK 8
#define NCOPY ((int)(NROWS / (RPW * WARPS_PER_BLK)))   // 3072 copy blocks
#define LSTR ((size_t)BATCH * RC)           // row index stride per layer
#define NWT (NL * RC * 256)                 // transposed weight elements

// Transposed weights: lane-coalesced for thread==j mapping.
__device__ float2 g_convT[NWT];             // [i][rc][j] -> (w0, w1)
__device__ float  g_fc1T[NWT];              // [i][rc][j]

__device__ __forceinline__ float sigf(float x) { return 1.0f / (1.0f + __expf(-x)); }

// ---------------------------------------------------------------------------
// WEIGHT TRANSPOSE: conv_w [i][j][rc][2] -> convT [i][rc][j] float2
//                   fc1_w  [j][i*64+rc]  -> fc1T  [i][rc][j]
// ---------------------------------------------------------------------------
__global__ void __launch_bounds__(NTHREADS)
transpose_weights_kernel(const float* __restrict__ conv_w,
                         const float* __restrict__ fc1_w)
{
    int idx = blockIdx.x * NTHREADS + threadIdx.x;   // ((i*64+rc)*256+j)
    if (idx >= NWT) return;
    int j    = idx & 255;
    int rcil = idx >> 8;
    int rc   = rcil & 63;
    int i    = rcil >> 6;
    const float* cw = conv_w + (((size_t)i * 256 + j) * 64 + rc) * 2;
    g_convT[idx] = make_float2(cw[0], cw[1]);
    g_fc1T[idx]  = fc1_w[(size_t)j * (NL * RC) + i * 64 + rc];
}

// Store one 128-float row (held as float4 v per lane) to dstq + R*129,
// realigned so the bulk goes out as one aligned STG.128 per lane.
__device__ __forceinline__ void store_row(float* __restrict__ dstq, size_t R,
                                          int lane, float4 v)
{
    float* base = dstq + R * 129;
    unsigned m = (unsigned)(R & 3);          // base misalignment in floats
    if (m == 0) {
        *(float4*)(base + 4 * lane) = v;
        return;
    }
    unsigned s = 4 - m;                      // shift: first aligned float index
    float nx = __shfl_down_sync(0xffffffffu, v.x, 1);
    float ny = __shfl_down_sync(0xffffffffu, v.y, 1);
    float nz = __shfl_down_sync(0xffffffffu, v.z, 1);
    float4 w;
    if (s == 1)      w = make_float4(v.y, v.z, v.w, nx);
    else if (s == 2) w = make_float4(v.z, v.w, nx, ny);
    else             w = make_float4(v.w, nx, ny, nz);
    if (lane < 31)
        *(float4*)(base + s + 4 * lane) = w; // 16B-aligned bulk
    if (lane == 0) {                         // head floats j = 0..s-1
        base[0] = v.x;
        if (s >= 2) base[1] = v.y;
        if (s >= 3) base[2] = v.z;
    }
    if (lane == 31) {                        // tail floats j = s+124..127
        base[127] = v.w;
        if (s <= 2) base[126] = v.z;
        if (s <= 1) base[125] = v.y;
    }
}

// ---------------------------------------------------------------------------
// COPY KERNEL: queues (.., 128) -> out queue region (.., 129), t < 128.
// (Proven: 313us standalone, 5.1 TB/s, occ 88%.)
// ---------------------------------------------------------------------------
__global__ void __launch_bounds__(NTHREADS)
queue_copy_kernel(const float* __restrict__ queues, float* __restrict__ out)
{
    const float4* __restrict__ src = (const float4*)queues;
    float* __restrict__ dstq = out + BATCH;
    const int lane = threadIdx.x & 31;
    size_t R = ((size_t)blockIdx.x * WARPS_PER_BLK + (threadIdx.x >> 5)) * RPW;

    #pragma unroll 1
    for (int it = 0; it < RPW / 4; it++, R += 4) {
        float4 v0 = __ldcs(&src[(R)     * 32 + lane]);
        float4 v1 = __ldcs(&src[(R + 1) * 32 + lane]);
        float4 v2 = __ldcs(&src[(R + 2) * 32 + lane]);
        float4 v3 = __ldcs(&src[(R + 3) * 32 + lane]);
        store_row(dstq, R,     lane, v0);
        store_row(dstq, R + 1, lane, v1);
        store_row(dstq, R + 2, lane, v2);
        store_row(dstq, R + 3, lane, v3);
    }
}

// ---------------------------------------------------------------------------
// COMPUTE KERNEL: recurrent WaveNet cell, TB=4 batch rows per block.
// Weights read lane-coalesced from transposed arrays; all 24 dilated queue
// slices prefetched into shared up front (static unroll, no spills).
// ---------------------------------------------------------------------------
__global__ void __launch_bounds__(NTHREADS)
wave_compute_kernel(const float* __restrict__ x,
                    const float* __restrict__ features,
                    const float* __restrict__ queues,
                    const float* __restrict__ fc_h_w,
                    const float* __restrict__ fc_h_b,
                    const float* __restrict__ fc_c_w,
                    const float* __restrict__ fc_c_b,
                    const float* __restrict__ conv_b,
                    const float* __restrict__ fc1_b,
                    const float* __restrict__ fc2_w,
                    const float* __restrict__ fc2_b,
                    float* __restrict__ out)
{
    __shared__ __align__(16) float s_h[TB][RC];
    __shared__ __align__(16) float s_c[TB][RC];
    __shared__ __align__(16) float s_pv[NL][TB][RC];   // 24 KB prefetched slices
    __shared__ float s_co[TB][4 * RC];

    const int tid = threadIdx.x;
    const int b0  = blockIdx.x * TB;
    const int j   = tid;
    const int t   = tid >> 6;
    const int r   = tid & 63;
    const int b   = b0 + t;

    // ---- prefetch ALL 24 layers' dilated queue values into shared ----
    {
        const size_t qbase = ((size_t)b * RC + r) * QL + QL;  // minus d below
        #pragma unroll
        for (int i = 0; i < NL; i++)
            s_pv[i][t][r] =
                __ldg(queues + qbase + (size_t)i * (LSTR * QL) - (1 << (i & 7)));
    }

    // ---- initial h, c = tanh(inp @ W^T + b), inp = [x, features] (33) ----
    float* __restrict__ outq = out + BATCH;
    const size_t ebase = (size_t)b * RC + r;   // entry-store row index base
    {
        const float* wh = fc_h_w + r * 33;
        const float* wc = fc_c_w + r * 33;
        float ah = fc_h_b[r], ac = fc_c_b[r];
        float xv = x[b];
        ah += xv * wh[0];
        ac += xv * wc[0];
        const float* fb = features + b * 32;
        #pragma unroll
        for (int k = 0; k < 32; k++) {
            float f = fb[k];
            ah += f * wh[1 + k];
            ac += f * wc[1 + k];
        }
        float h0 = tanhf(ah);
        s_h[t][r] = h0;
        s_c[t][r] = tanhf(ac);
        outq[ebase * 129 + QL] = h0;           // entry for layer 0
    }

    float yacc[TB];
    #pragma unroll
    for (int tt = 0; tt < TB; tt++) yacc[tt] = fc1_b[j];
    __syncthreads();

    const float2* __restrict__ wcv = g_convT + j;   // + (i*64+rc)*256
    const float*  __restrict__ wf1 = g_fc1T  + j;

    for (int i = 0; i < NL; i++) {
        // ---- conv: co[tt][j] = prev @ W0^T + h @ W1^T + bias ----
        float acc[TB];
        {
            float bias = __ldg(conv_b + i * 256 + j);
            #pragma unroll
            for (int tt = 0; tt < TB; tt++) acc[tt] = bias;
        }
        const float2* wci = wcv + (size_t)i * (RC * 256);
        #pragma unroll 4
        for (int rc = 0; rc < RC; rc += 4) {
            float2 w0 = __ldg(&wci[(rc + 0) << 8]);
            float2 w1 = __ldg(&wci[(rc + 1) << 8]);
            float2 w2 = __ldg(&wci[(rc + 2) << 8]);
            float2 w3 = __ldg(&wci[(rc + 3) << 8]);
            #pragma unroll
            for (int tt = 0; tt < TB; tt++) {
                float4 p  = *(const float4*)&s_pv[i][tt][rc];
                float4 hh = *(const float4*)&s_h[tt][rc];
                float a = acc[tt];
                a += p.x * w0.x + hh.x * w0.y;
                a += p.y * w1.x + hh.y * w1.y;
                a += p.z * w2.x + hh.z * w2.y;
                a += p.w * w3.x + hh.w * w3.y;
                acc[tt] = a;
            }
        }
        #pragma unroll
        for (int tt = 0; tt < TB; tt++) s_co[tt][j] = acc[tt];
        __syncthreads();

        // ---- gate update (one element per thread); write next entry ----
        {
            float ig = s_co[t][r];
            float cf = s_co[t][RC + r];
            float cg = s_co[t][2 * RC + r];
            float eg = s_co[t][3 * RC + r];
            float c = sigf(ig) * s_c[t][r] + tanhf(cf) * sigf(cg);
            float h = sigf(eg) * tanhf(c);
            s_c[t][r] = c;
            s_h[t][r] = h;
            if (i + 1 < NL)                    // entry_h for layer i+1
                outq[(ebase + (size_t)(i + 1) * LSTR) * 129 + QL] = h;
        }
        __syncthreads();

        // ---- incremental fc1: yacc[tt] += h_new[tt] @ fc1T[i][:,j] ----
        const float* f1i = wf1 + (size_t)i * (RC * 256);
        #pragma unroll 4
        for (int rc = 0; rc < RC; rc += 4) {
            float a0 = __ldg(&f1i[(rc + 0) << 8]);
            float a1 = __ldg(&f1i[(rc + 1) << 8]);
            float a2 = __ldg(&f1i[(rc + 2) << 8]);
            float a3 = __ldg(&f1i[(rc + 3) << 8]);
            #pragma unroll
            for (int tt = 0; tt < TB; tt++) {
                float4 hh = *(const float4*)&s_h[tt][rc];
                yacc[tt] += hh.x * a0 + hh.y * a1 + hh.z * a2 + hh.w * a3;
            }
        }
        // no barrier: next conv's s_co writes are gated by the post-conv
        // barrier; s_h is only re-written after that barrier
    }

    // ---- fc2: h_hat[b] = relu(y) @ fc2_w^T + fc2_b ----
    #pragma unroll
    for (int tt = 0; tt < TB; tt++)
        s_co[tt][j] = fmaxf(yacc[tt], 0.0f) * fc2_w[j];
    __syncthreads();

    int w = tid >> 5, lane = tid & 31;
    if (w < TB) {                        // warps 0..3 reduce the TB rows
        float s = 0.0f;
        #pragma unroll
        for (int k = 0; k < 8; k++) s += s_co[w][lane + k * 32];
        #pragma unroll
        for (int o = 16; o > 0; o >>= 1) s += __shfl_xor_sync(0xffffffffu, s, o);
        if (lane == 0) out[b0 + w] = s + fc2_b[0];
    }
}

extern "C" void kernel_launch(void* const* d_in, const int* in_sizes, int n_in,
                              void* d_out, int out_size)
{
    const float* x        = (const float*)d_in[0];
    const float* features = (const float*)d_in[1];
    const float* queues   = (const float*)d_in[2];
    const float* fc_h_w   = (const float*)d_in[3];
    const float* fc_h_b   = (const float*)d_in[4];
    const float* fc_c_w   = (const float*)d_in[5];
    const float* fc_c_b   = (const float*)d_in[6];
    const float* conv_w   = (const float*)d_in[7];
    const float* conv_b   = (const float*)d_in[8];
    const float* fc1_w    = (const float*)d_in[9];
    const float* fc1_b    = (const float*)d_in[10];
    const float* fc2_w    = (const float*)d_in[11];
    const float* fc2_b    = (const float*)d_in[12];
    float* out = (float*)d_out;

    // Serial: transpose (tiny) -> compute (weights warm in L2) -> copy.
    transpose_weights_kernel<<<(NWT + NTHREADS - 1) / NTHREADS, NTHREADS>>>(
        conv_w, fc1_w);

    wave_compute_kernel<<<NCOMP, NTHREADS>>>(
        x, features, queues, fc_h_w, fc_h_b, fc_c_w, fc_c_b,
        conv_b, fc1_b, fc2_w, fc2_b, out);

    queue_copy_kernel<<<NCOPY, NTHREADS>>>(queues, out);
}

// round 8
// speedup vs baseline: 2.2017x; 1.2381x over previous
#include <cuda_runtime.h>

#define BATCH 1024
#define RC 64
#define NL 24
#define QL 128
#define TB 4                     // batch rows per compute block
#define NCOMP (BATCH / TB)       // 256 compute blocks
#define CTHREADS 512             // compute block threads (2 groups of 256)
#define NTHREADS 256
#define NQ ((size_t)NL * BATCH * RC * QL)   // 201326592 queue elements
#define NROWS (NQ / 128)                    // 1572864 rows of 128 floats
#define RPW 64                              // rows per copy warp
#define WARPS_PER_BLK 8
#define NCOPY ((int)(NROWS / (RPW * WARPS_PER_BLK)))   // 3072 copy blocks
#define LSTR ((size_t)BATCH * RC)           // row index stride per layer
#define NWT (NL * RC * 256)                 // transposed weight elements

// Transposed weights: lane-coalesced for thread==j mapping.
__device__ float2 g_convT[NWT];             // [i][rc][j] -> (w0, w1)
__device__ float  g_fc1T[NWT];              // [i][rc][j]

__device__ __forceinline__ float sigf(float x) { return 1.0f / (1.0f + __expf(-x)); }

// ---------------------------------------------------------------------------
// WEIGHT TRANSPOSE: conv_w [i][j][rc][2] -> convT [i][rc][j] float2
//                   fc1_w  [j][i*64+rc]  -> fc1T  [i][rc][j]
// ---------------------------------------------------------------------------
__global__ void __launch_bounds__(NTHREADS)
transpose_weights_kernel(const float* __restrict__ conv_w,
                         const float* __restrict__ fc1_w)
{
    int idx = blockIdx.x * NTHREADS + threadIdx.x;   // ((i*64+rc)*256+j)
    if (idx >= NWT) return;
    int j    = idx & 255;
    int rcil = idx >> 8;
    int rc   = rcil & 63;
    int i    = rcil >> 6;
    const float* cw = conv_w + (((size_t)i * 256 + j) * 64 + rc) * 2;
    g_convT[idx] = make_float2(cw[0], cw[1]);
    g_fc1T[idx]  = fc1_w[(size_t)j * (NL * RC) + i * 64 + rc];
}

// Store one 128-float row (held as float4 v per lane) to dstq + R*129,
// realigned so the bulk goes out as one aligned STG.128 per lane.
__device__ __forceinline__ void store_row(float* __restrict__ dstq, size_t R,
                                          int lane, float4 v)
{
    float* base = dstq + R * 129;
    unsigned m = (unsigned)(R & 3);          // base misalignment in floats
    if (m == 0) {
        *(float4*)(base + 4 * lane) = v;
        return;
    }
    unsigned s = 4 - m;                      // shift: first aligned float index
    float nx = __shfl_down_sync(0xffffffffu, v.x, 1);
    float ny = __shfl_down_sync(0xffffffffu, v.y, 1);
    float nz = __shfl_down_sync(0xffffffffu, v.z, 1);
    float4 w;
    if (s == 1)      w = make_float4(v.y, v.z, v.w, nx);
    else if (s == 2) w = make_float4(v.z, v.w, nx, ny);
    else             w = make_float4(v.w, nx, ny, nz);
    if (lane < 31)
        *(float4*)(base + s + 4 * lane) = w; // 16B-aligned bulk
    if (lane == 0) {                         // head floats j = 0..s-1
        base[0] = v.x;
        if (s >= 2) base[1] = v.y;
        if (s >= 3) base[2] = v.z;
    }
    if (lane == 31) {                        // tail floats j = s+124..127
        base[127] = v.w;
        if (s <= 2) base[126] = v.z;
        if (s <= 1) base[125] = v.y;
    }
}

// ---------------------------------------------------------------------------
// COPY KERNEL: queues (.., 128) -> out queue region (.., 129), t < 128.
// (Proven: 313us standalone, 5.1 TB/s, occ 88%.)
// ---------------------------------------------------------------------------
__global__ void __launch_bounds__(NTHREADS)
queue_copy_kernel(const float* __restrict__ queues, float* __restrict__ out)
{
    const float4* __restrict__ src = (const float4*)queues;
    float* __restrict__ dstq = out + BATCH;
    const int lane = threadIdx.x & 31;
    size_t R = ((size_t)blockIdx.x * WARPS_PER_BLK + (threadIdx.x >> 5)) * RPW;

    #pragma unroll 1
    for (int it = 0; it < RPW / 4; it++, R += 4) {
        float4 v0 = __ldcs(&src[(R)     * 32 + lane]);
        float4 v1 = __ldcs(&src[(R + 1) * 32 + lane]);
        float4 v2 = __ldcs(&src[(R + 2) * 32 + lane]);
        float4 v3 = __ldcs(&src[(R + 3) * 32 + lane]);
        store_row(dstq, R,     lane, v0);
        store_row(dstq, R + 1, lane, v1);
        store_row(dstq, R + 2, lane, v2);
        store_row(dstq, R + 3, lane, v3);
    }
}

// ---------------------------------------------------------------------------
// COMPUTE KERNEL: 512 threads, TB=4 batch rows. Group g = tid>>8 handles
// rows {2g, 2g+1} with channel j = tid&255. Halves each thread's serial
// FMA chain and doubles warps/SM vs the 256-thread version.
// ---------------------------------------------------------------------------
__global__ void __launch_bounds__(CTHREADS, 2)
wave_compute_kernel(const float* __restrict__ x,
                    const float* __restrict__ features,
                    const float* __restrict__ queues,
                    const float* __restrict__ fc_h_w,
                    const float* __restrict__ fc_h_b,
                    const float* __restrict__ fc_c_w,
                    const float* __restrict__ fc_c_b,
                    const float* __restrict__ conv_b,
                    const float* __restrict__ fc1_b,
                    const float* __restrict__ fc2_w,
                    const float* __restrict__ fc2_b,
                    float* __restrict__ out)
{
    __shared__ __align__(16) float s_h[TB][RC];
    __shared__ __align__(16) float s_c[TB][RC];
    __shared__ __align__(16) float s_pv[NL][TB][RC];   // 24 KB prefetched slices
    __shared__ float s_co[TB][4 * RC];

    const int tid = threadIdx.x;
    const int b0  = blockIdx.x * TB;
    const int g   = tid >> 8;          // row-group: handles tt = 2g, 2g+1
    const int j   = tid & 255;         // output channel
    const int t0  = g * 2;

    // ---- prefetch ALL 24 layers' dilated queue values into shared ----
    for (int idx = tid; idx < NL * TB * RC; idx += CTHREADS) {
        int i = idx >> 8;
        int t = (idx >> 6) & 3;
        int r = idx & 63;
        s_pv[i][t][r] = __ldg(queues
            + (((size_t)(b0 + t) * RC + r) + (size_t)i * LSTR) * QL
            + QL - (1 << (i & 7)));
    }

    // ---- initial h, c = tanh(inp @ W^T + b)  (threads 0..255 only) ----
    float* __restrict__ outq = out + BATCH;
    size_t ebase = 0;
    if (tid < 256) {
        int t = tid >> 6, r = tid & 63;
        int b = b0 + t;
        ebase = (size_t)b * RC + r;
        const float* wh = fc_h_w + r * 33;
        const float* wc = fc_c_w + r * 33;
        float ah = fc_h_b[r], ac = fc_c_b[r];
        float xv = x[b];
        ah += xv * wh[0];
        ac += xv * wc[0];
        const float* fb = features + b * 32;
        #pragma unroll
        for (int k = 0; k < 32; k++) {
            float f = fb[k];
            ah += f * wh[1 + k];
            ac += f * wc[1 + k];
        }
        float h0 = tanhf(ah);
        s_h[t][r] = h0;
        s_c[t][r] = tanhf(ac);
        outq[ebase * 129 + QL] = h0;           // entry for layer 0
    }

    float yacc0 = fc1_b[j], yacc1 = yacc0;
    __syncthreads();

    const float2* __restrict__ wcv = g_convT + j;   // + (i*64+rc)*256
    const float*  __restrict__ wf1 = g_fc1T  + j;

    for (int i = 0; i < NL; i++) {
        // ---- conv: co[tt][j] = prev @ W0^T + h @ W1^T + bias ----
        float acc0, acc1;
        acc0 = acc1 = __ldg(conv_b + i * 256 + j);
        const float2* wci = wcv + (size_t)i * (RC * 256);
        #pragma unroll 4
        for (int rc = 0; rc < RC; rc += 4) {
            float2 w0 = __ldg(&wci[(rc + 0) << 8]);
            float2 w1 = __ldg(&wci[(rc + 1) << 8]);
            float2 w2 = __ldg(&wci[(rc + 2) << 8]);
            float2 w3 = __ldg(&wci[(rc + 3) << 8]);
            {
                float4 p  = *(const float4*)&s_pv[i][t0][rc];
                float4 hh = *(const float4*)&s_h[t0][rc];
                acc0 += p.x * w0.x + hh.x * w0.y;
                acc0 += p.y * w1.x + hh.y * w1.y;
                acc0 += p.z * w2.x + hh.z * w2.y;
                acc0 += p.w * w3.x + hh.w * w3.y;
            }
            {
                float4 p  = *(const float4*)&s_pv[i][t0 + 1][rc];
                float4 hh = *(const float4*)&s_h[t0 + 1][rc];
                acc1 += p.x * w0.x + hh.x * w0.y;
                acc1 += p.y * w1.x + hh.y * w1.y;
                acc1 += p.z * w2.x + hh.z * w2.y;
                acc1 += p.w * w3.x + hh.w * w3.y;
            }
        }
        s_co[t0][j]     = acc0;
        s_co[t0 + 1][j] = acc1;
        __syncthreads();

        // ---- gate update (threads 0..255); write next layer's entry ----
        if (tid < 256) {
            int t = tid >> 6, r = tid & 63;
            float ig = s_co[t][r];
            float cf = s_co[t][RC + r];
            float cg = s_co[t][2 * RC + r];
            float eg = s_co[t][3 * RC + r];
            float c = sigf(ig) * s_c[t][r] + tanhf(cf) * sigf(cg);
            float h = sigf(eg) * tanhf(c);
            s_c[t][r] = c;
            s_h[t][r] = h;
            if (i + 1 < NL)                    // entry_h for layer i+1
                outq[(ebase + (size_t)(i + 1) * LSTR) * 129 + QL] = h;
        }
        __syncthreads();

        // ---- incremental fc1: yacc += h_new[tt] @ fc1T[i][:,j] ----
        const float* f1i = wf1 + (size_t)i * (RC * 256);
        #pragma unroll 4
        for (int rc = 0; rc < RC; rc += 4) {
            float a0 = __ldg(&f1i[(rc + 0) << 8]);
            float a1 = __ldg(&f1i[(rc + 1) << 8]);
            float a2 = __ldg(&f1i[(rc + 2) << 8]);
            float a3 = __ldg(&f1i[(rc + 3) << 8]);
            {
                float4 hh = *(const float4*)&s_h[t0][rc];
                yacc0 += hh.x * a0 + hh.y * a1 + hh.z * a2 + hh.w * a3;
            }
            {
                float4 hh = *(const float4*)&s_h[t0 + 1][rc];
                yacc1 += hh.x * a0 + hh.y * a1 + hh.z * a2 + hh.w * a3;
            }
        }
        // no barrier: s_co rewrites are fenced by the post-conv barrier;
        // s_h is only re-written after that barrier
    }

    // ---- fc2: h_hat[b] = relu(y) @ fc2_w^T + fc2_b ----
    {
        float fw = fc2_w[j];
        s_co[t0][j]     = fmaxf(yacc0, 0.0f) * fw;
        s_co[t0 + 1][j] = fmaxf(yacc1, 0.0f) * fw;
    }
    __syncthreads();

    int w = tid >> 5, lane = tid & 31;
    if (w < TB) {                        // warps 0..3 reduce the TB rows
        float s = 0.0f;
        #pragma unroll
        for (int k = 0; k < 8; k++) s += s_co[w][lane + k * 32];
        #pragma unroll
        for (int o = 16; o > 0; o >>= 1) s += __shfl_xor_sync(0xffffffffu, s, o);
        if (lane == 0) out[b0 + w] = s + fc2_b[0];
    }
}

extern "C" void kernel_launch(void* const* d_in, const int* in_sizes, int n_in,
                              void* d_out, int out_size)
{
    const float* x        = (const float*)d_in[0];
    const float* features = (const float*)d_in[1];
    const float* queues   = (const float*)d_in[2];
    const float* fc_h_w   = (const float*)d_in[3];
    const float* fc_h_b   = (const float*)d_in[4];
    const float* fc_c_w   = (const float*)d_in[5];
    const float* fc_c_b   = (const float*)d_in[6];
    const float* conv_w   = (const float*)d_in[7];
    const float* conv_b   = (const float*)d_in[8];
    const float* fc1_w    = (const float*)d_in[9];
    const float* fc1_b    = (const float*)d_in[10];
    const float* fc2_w    = (const float*)d_in[11];
    const float* fc2_b    = (const float*)d_in[12];
    float* out = (float*)d_out;

    // Serial: transpose (tiny) -> compute (weights warm in L2) -> copy.
    transpose_weights_kernel<<<(NWT + NTHREADS - 1) / NTHREADS, NTHREADS>>>(
        conv_w, fc1_w);

    wave_compute_kernel<<<NCOMP, CTHREADS>>>(
        x, features, queues, fc_h_w, fc_h_b, fc_c_w, fc_c_b,
        conv_b, fc1_b, fc2_w, fc2_b, out);

    queue_copy_kernel<<<NCOPY, NTHREADS>>>(queues, out);
}